// round 1
// baseline (speedup 1.0000x reference)
#include <cuda_runtime.h>
#include <cuda_bf16.h>
#include <math.h>

#define N384 384
#define NPIX (384*384)
#define PI_F 3.14159265358979323846f

// -------- scratch (static __device__ arrays; allocation is forbidden) --------
__device__ float2 g_A  [12*NPIX];   // forward row-pass result
__device__ float2 g_Xs [12*NPIX];   // shifted spectrum  [b*3+d][h][w]
__device__ float2 g_Att[ 4*NPIX];   // attended (shifted coords)
__device__ float2 g_Tmp[36*NPIX];   // inverse column-pass result
__device__ float  g_P  [36*NPIX];   // Re(IFFT2(mask*attended)) * (-1)^(n+m)
__device__ float  g_Cv [12*NPIX];   // spatial conv  [b][o][h][w]

__device__ __forceinline__ float2 cmul(float2 a, float2 b) {
    return make_float2(a.x*b.x - a.y*b.y, a.x*b.y + a.y*b.x);
}

// ---------------- 384-pt Stockham FFT (radix-3 then 7x radix-2) --------------
// NC independent transforms in smem, layout s[c*384 + elem]. Result ends in s0.
// dir = -1 forward, +1 inverse (exponent sign). No normalization.
template<int NC>
__device__ void fft384_multi(float2* s0, float2* s1, int tid, int nt, float dir)
{
    __syncthreads();
    // Stage: radix-3, n=384, s=1, m=128
    {
        const float th0 = dir * (2.0f * PI_F / 384.0f);
        const float s3  = dir * 0.8660254037844386f;   // omega = -1/2 + i*s3
        const int total = NC * 128;
        for (int idx = tid; idx < total; idx += nt) {
            int c = idx >> 7;            // /128
            int p = idx & 127;
            const float2* x = s0 + c*N384;
            float2*       y = s1 + c*N384;
            float2 a = x[p], b = x[p+128], cc = x[p+256];
            float t1x = b.x+cc.x, t1y = b.y+cc.y;
            float t2x = b.x-cc.x, t2y = b.y-cc.y;
            float2 x0 = make_float2(a.x+t1x, a.y+t1y);
            float ux = a.x - 0.5f*t1x, uy = a.y - 0.5f*t1y;
            float vx = -s3*t2y,        vy =  s3*t2x;
            float2 x1 = make_float2(ux+vx, uy+vy);
            float2 x2 = make_float2(ux-vx, uy-vy);
            float cw, sw; __sincosf(th0 * (float)p, &sw, &cw);
            float2 w1 = make_float2(cw, sw);
            float2 w2 = cmul(w1, w1);
            y[3*p  ] = x0;
            y[3*p+1] = cmul(x1, w1);
            y[3*p+2] = cmul(x2, w2);
        }
        __syncthreads();
    }
    // 7 radix-2 stages: (n,s) = (128,3)...(2,192);  m*s == 192 constant
    int n = 128, s = 3;
    float2 *src = s1, *dst = s0;
    for (int st = 0; st < 7; st++) {
        int m = n >> 1;
        float th0 = dir * (2.0f * PI_F / (float)n);
        const int total = NC * 192;
        for (int idx = tid; idx < total; idx += nt) {
            int c = idx / 192;
            int r = idx - c*192;
            int p = r / s, q = r - p*s;
            const float2* x = src + c*N384;
            float2*       y = dst + c*N384;
            float2 a = x[q + s*p], b = x[q + s*(p+m)];
            float2 apb = make_float2(a.x+b.x, a.y+b.y);
            float2 amb = make_float2(a.x-b.x, a.y-b.y);
            float cw, sw; __sincosf(th0 * (float)p, &sw, &cw);
            float2 t = make_float2(amb.x*cw - amb.y*sw, amb.x*sw + amb.y*cw);
            y[q + s*(2*p)  ] = apb;
            y[q + s*(2*p+1)] = t;
        }
        __syncthreads();
        float2* tt = src; src = dst; dst = tt;
        n >>= 1; s <<= 1;
    }
    // 8 stages total -> result in s0
}

// ------------------------- forward: row pass ---------------------------------
__global__ void k_fwd_row(const float* __restrict__ x)
{
    __shared__ float2 s0[N384], s1[N384];
    int blk = blockIdx.x;
    int img = blk / N384;            // img = b*3 + d (shifted indices)
    int row = blk - img*N384;
    int b = img / 3, d = img - b*3;
    int bs = (b + 2) & 3;            // fftshift over batch axis (n=4)
    int ds = (d + 2) % 3;            // fftshift over channel axis (n=3): src=(d-1)%3
    const float* xr = x + ((size_t)(bs*3 + ds)*N384 + row)*N384;
    for (int w = threadIdx.x; w < N384; w += blockDim.x)
        s0[w] = make_float2(xr[w], 0.f);
    fft384_multi<1>(s0, s1, threadIdx.x, blockDim.x, -1.f);
    float2* out = g_A + ((size_t)img*N384 + row)*N384;
    for (int w = threadIdx.x; w < N384; w += blockDim.x)
        out[w] = s0[w];
}

// ------------------------- forward: column pass (+h,w shift) -----------------
__global__ void k_fwd_col()
{
    __shared__ float2 s0[4*N384], s1[4*N384];
    int img  = blockIdx.x / 96;
    int tile = blockIdx.x - img*96;
    int c0 = tile * 4;
    const float2* A = g_A + (size_t)img*NPIX;
    for (int idx = threadIdx.x; idx < 4*N384; idx += blockDim.x) {
        int h = idx >> 2, c = idx & 3;
        s0[c*N384 + h] = A[h*N384 + c0 + c];
    }
    fft384_multi<4>(s0, s1, threadIdx.x, blockDim.x, -1.f);
    float2* Xs = g_Xs + (size_t)img*NPIX;
    for (int idx = threadIdx.x; idx < 4*N384; idx += blockDim.x) {
        int hh = idx >> 2, c = idx & 3;
        int h2 = hh + 192; if (h2 >= N384) h2 -= N384;
        int w2 = c0 + c + 192; if (w2 >= N384) w2 -= N384;
        Xs[h2*N384 + w2] = s0[c*N384 + hh];
    }
}

// ---------------- attention MLP + log-Gabor bank + attended ------------------
__global__ void k_attn(const float* __restrict__ theta, const float* __restrict__ sigma,
                       const float* __restrict__ f0,    const float* __restrict__ theta0,
                       const float* __restrict__ w1,    const float* __restrict__ b1,
                       const float* __restrict__ w2,    const float* __restrict__ b2)
{
    __shared__ float sw1[192], sb1[64], sw2[576], sb2[9];
    __shared__ float sth[27], ssg[27], sf0[27], st0[27];
    int tid = threadIdx.x;
    for (int i = tid; i < 192; i += 256) sw1[i] = w1[i];
    for (int i = tid; i < 576; i += 256) sw2[i] = w2[i];
    if (tid < 64) sb1[tid] = b1[tid];
    if (tid < 9)  sb2[tid] = b2[tid];
    if (tid < 27) { sth[tid]=theta[tid]; ssg[tid]=sigma[tid]; sf0[tid]=f0[tid]; st0[tid]=theta0[tid]; }
    __syncthreads();

    int p = blockIdx.x*256 + tid;                 // grid covers 147456 exactly
    int h = p / N384, w = p - h*N384;
    float yy = -1.f + (2.f/383.f) * (float)h;
    float xx = -1.f + (2.f/383.f) * (float)w;
    float r   = sqrtf(xx*xx + yy*yy + 1e-6f);
    float phi = atan2f(yy, xx);

    float filt[27];
    #pragma unroll
    for (int i = 0; i < 27; i++) {
        float lf0 = logf(sf0[i]);
        float lr  = logf(r - lf0);
        float ls  = logf(ssg[i]);
        float lg  = expf(-(lr*lr) / (2.f*ls*ls));
        float dph = phi - sth[i];
        float ang = expf(-(dph*dph) / (2.f*st0[i]*st0[i]));
        filt[i] = lg * ang;
    }

    for (int b = 0; b < 4; b++) {
        float2 X[3]; float mag[3];
        #pragma unroll
        for (int d = 0; d < 3; d++) {
            X[d] = g_Xs[(size_t)(b*3+d)*NPIX + p];
            mag[d] = sqrtf(X[d].x*X[d].x + X[d].y*X[d].y);
        }
        float logit[9];
        #pragma unroll
        for (int o = 0; o < 9; o++) logit[o] = sb2[o];
        for (int j = 0; j < 64; j++) {
            float t = sb1[j] + sw1[j*3]*mag[0] + sw1[j*3+1]*mag[1] + sw1[j*3+2]*mag[2];
            t = fmaxf(t, 0.f);
            #pragma unroll
            for (int o = 0; o < 9; o++) logit[o] = fmaf(sw2[o*64+j], t, logit[o]);
        }
        float mx = logit[0];
        #pragma unroll
        for (int o = 1; o < 9; o++) mx = fmaxf(mx, logit[o]);
        float att[9], ssum = 0.f;
        #pragma unroll
        for (int o = 0; o < 9; o++) { att[o] = expf(logit[o]-mx); ssum += att[o]; }
        float inv = 1.f / ssum;
        float wg0=0.f, wg1=0.f, wg2=0.f;
        #pragma unroll
        for (int sc = 0; sc < 9; sc++) {
            float a = att[sc] * inv;
            wg0 = fmaf(a, filt[sc*3+0], wg0);
            wg1 = fmaf(a, filt[sc*3+1], wg1);
            wg2 = fmaf(a, filt[sc*3+2], wg2);
        }
        float2 acc;
        acc.x = X[0].x*wg0 + X[1].x*wg1 + X[2].x*wg2;
        acc.y = X[0].y*wg0 + X[1].y*wg1 + X[2].y*wg2;
        g_Att[(size_t)b*NPIX + p] = acc;
    }
}

// ---------------- inverse: column pass with band mask ------------------------
__global__ void k_inv_col(const float* __restrict__ band)
{
    __shared__ float2 s0[4*N384], s1[4*N384];
    int plane = blockIdx.x / 96;
    int tile  = blockIdx.x - plane*96;
    int kap  = plane / 12;
    int rest = plane - kap*12;
    int del  = rest / 4;
    int beta = rest - del*4;
    float b0 = band[(kap*3+del)*2+0], b1 = band[(kap*3+del)*2+1];
    int si = (int)floorf((b0+1.f)*0.5f*384.f);
    int ei = (int)floorf((b1+1.f)*0.5f*384.f);
    int c0 = tile * 4;

    float2* T = g_Tmp + (size_t)plane*NPIX;
    bool empty = (si >= ei) || (c0 >= ei) || (c0+4 <= si);
    if (empty) {
        float2 z = make_float2(0.f, 0.f);
        for (int idx = threadIdx.x; idx < 4*N384; idx += blockDim.x) {
            int n = idx >> 2, c = idx & 3;
            T[n*N384 + c0 + c] = z;
        }
        return;
    }
    const float2* At = g_Att + (size_t)beta*NPIX;
    for (int idx = threadIdx.x; idx < 4*N384; idx += blockDim.x) {
        int h = idx >> 2, c = idx & 3;
        int wc = c0 + c;
        float2 v = make_float2(0.f, 0.f);
        if (wc >= si && wc < ei && h >= si && h < ei)
            v = At[h*N384 + wc];
        s0[c*N384 + h] = v;
    }
    fft384_multi<4>(s0, s1, threadIdx.x, blockDim.x, +1.f);
    const float sc = 1.f/384.f;
    for (int idx = threadIdx.x; idx < 4*N384; idx += blockDim.x) {
        int n = idx >> 2, c = idx & 3;
        float2 v = s0[c*N384 + n];
        T[n*N384 + c0 + c] = make_float2(v.x*sc, v.y*sc);
    }
}

// ---------------- inverse: row pass, real part, (-1)^(n+m) sign --------------
__global__ void k_inv_row()
{
    __shared__ float2 s0[N384], s1[N384];
    int plane = blockIdx.x / N384;
    int n     = blockIdx.x - plane*N384;
    const float2* T = g_Tmp + (size_t)plane*NPIX + (size_t)n*N384;
    for (int w = threadIdx.x; w < N384; w += blockDim.x) s0[w] = T[w];
    fft384_multi<1>(s0, s1, threadIdx.x, blockDim.x, +1.f);
    float* P = g_P + (size_t)plane*NPIX + (size_t)n*N384;
    const float sc = 1.f/384.f;
    for (int w = threadIdx.x; w < N384; w += blockDim.x) {
        float v = s0[w].x * sc;
        if ((n + w) & 1) v = -v;
        P[w] = v;
    }
}

// ---------------- spatial 3x3 conv -------------------------------------------
__global__ void k_conv(const float* __restrict__ x, const float* __restrict__ cw)
{
    int t = blockIdx.x*256 + threadIdx.x;
    if (t >= 12*NPIX) return;
    int w = t % N384;
    int h = (t / N384) % N384;
    int o = (t / NPIX) % 3;
    int b = t / (3*NPIX);
    float acc = 0.f;
    #pragma unroll
    for (int i = 0; i < 3; i++) {
        const float* xp = x + (size_t)(b*3+i)*NPIX;
        #pragma unroll
        for (int kh = 0; kh < 3; kh++) {
            int hh = h + kh - 1;
            if (hh < 0 || hh >= N384) continue;
            #pragma unroll
            for (int kw = 0; kw < 3; kw++) {
                int ww = w + kw - 1;
                if (ww < 0 || ww >= N384) continue;
                acc = fmaf(xp[hh*N384+ww], cw[((o*3+i)*3+kh)*3+kw], acc);
            }
        }
    }
    g_Cv[t] = acc;
}

// ---------------- final assembly ---------------------------------------------
__global__ void k_out(float* __restrict__ out, const float* __restrict__ mixing)
{
    int comb = blockIdx.y;                  // a*36 + co*12 + b*3 + ci   (144)
    int ci = comb % 3;
    int b  = (comb / 3) & 3;
    int co = (comb / 12) % 3;
    int kap = (co + 1) % 3, del = (ci + 1) % 3, beta = (b + 2) & 3;
    const float* P  = g_P  + (size_t)((kap*3+del)*4 + beta) * NPIX;
    const float* xs = g_Cv + (size_t)(b*3 + ci) * NPIX;
    float mix = mixing[0];
    int p = blockIdx.x*256 + threadIdx.x;
    out[(size_t)comb*NPIX + p] = mix * P[p] + (1.f - mix) * xs[p];
}

// ------------------------------------------------------------------
extern "C" void kernel_launch(void* const* d_in, const int* in_sizes, int n_in,
                              void* d_out, int out_size)
{
    const float* x      = (const float*)d_in[0];
    const float* theta  = (const float*)d_in[1];
    const float* sigma  = (const float*)d_in[2];
    const float* f0     = (const float*)d_in[3];
    const float* theta0 = (const float*)d_in[4];
    const float* aw1    = (const float*)d_in[5];
    const float* ab1    = (const float*)d_in[6];
    const float* aw2    = (const float*)d_in[7];
    const float* ab2    = (const float*)d_in[8];
    const float* convw  = (const float*)d_in[9];
    const float* mixing = (const float*)d_in[10];
    const float* band   = (const float*)d_in[11];
    float* out = (float*)d_out;

    k_fwd_row<<<12*N384, 128>>>(x);
    k_fwd_col<<<12*96, 256>>>();
    k_attn<<<NPIX/256, 256>>>(theta, sigma, f0, theta0, aw1, ab1, aw2, ab2);
    k_inv_col<<<36*96, 256>>>(band);
    k_inv_row<<<36*N384, 128>>>();
    k_conv<<<(12*NPIX+255)/256, 256>>>(x, convw);
    k_out<<<dim3(NPIX/256, 144), 256>>>(out, mixing);
}

// round 3
// speedup vs baseline: 1.4598x; 1.4598x over previous
#include <cuda_runtime.h>
#include <cuda_bf16.h>
#include <math.h>

#define N384 384
#define NPIX (384*384)
#define PI_F 3.14159265358979323846f

// -------- scratch (static __device__ arrays; allocation is forbidden) --------
__device__ float2 g_A  [12*NPIX];   // forward row-pass result
__device__ float2 g_Xs [12*NPIX];   // shifted spectrum  [b*3+d][h][w]
__device__ float2 g_Att[ 4*NPIX];   // attended (shifted coords)
__device__ float2 g_Tmp[36*NPIX];   // inverse column-pass result (band cols only valid)
__device__ float  g_Cv [12*NPIX];   // spatial conv  [b][o][h][w]

__device__ __forceinline__ float2 cmul(float2 a, float2 b) {
    return make_float2(a.x*b.x - a.y*b.y, a.x*b.y + a.y*b.x);
}

// ---------------- 384-pt Stockham FFT (radix-3 then 7x radix-2) --------------
// NC independent transforms in smem, layout s[c*384 + elem]. Result ends in s0.
// dir = -1 forward, +1 inverse (exponent sign). No normalization.
template<int NC>
__device__ void fft384_multi(float2* s0, float2* s1, int tid, int nt, float dir)
{
    __syncthreads();
    // Stage: radix-3, n=384, s=1, m=128
    {
        const float th0 = dir * (2.0f * PI_F / 384.0f);
        const float s3  = dir * 0.8660254037844386f;
        const int total = NC * 128;
        for (int idx = tid; idx < total; idx += nt) {
            int c = idx >> 7;
            int p = idx & 127;
            const float2* x = s0 + c*N384;
            float2*       y = s1 + c*N384;
            float2 a = x[p], b = x[p+128], cc = x[p+256];
            float t1x = b.x+cc.x, t1y = b.y+cc.y;
            float t2x = b.x-cc.x, t2y = b.y-cc.y;
            float2 x0 = make_float2(a.x+t1x, a.y+t1y);
            float ux = a.x - 0.5f*t1x, uy = a.y - 0.5f*t1y;
            float vx = -s3*t2y,        vy =  s3*t2x;
            float2 x1 = make_float2(ux+vx, uy+vy);
            float2 x2 = make_float2(ux-vx, uy-vy);
            float cw, sw; __sincosf(th0 * (float)p, &sw, &cw);
            float2 w1 = make_float2(cw, sw);
            float2 w2 = cmul(w1, w1);
            y[3*p  ] = x0;
            y[3*p+1] = cmul(x1, w1);
            y[3*p+2] = cmul(x2, w2);
        }
        __syncthreads();
    }
    int n = 128, s = 3;
    float2 *src = s1, *dst = s0;
    for (int st = 0; st < 7; st++) {
        int m = n >> 1;
        float th0 = dir * (2.0f * PI_F / (float)n);
        const int total = NC * 192;
        for (int idx = tid; idx < total; idx += nt) {
            int c = idx / 192;
            int r = idx - c*192;
            int p = r / s, q = r - p*s;
            const float2* x = src + c*N384;
            float2*       y = dst + c*N384;
            float2 a = x[q + s*p], b = x[q + s*(p+m)];
            float2 apb = make_float2(a.x+b.x, a.y+b.y);
            float2 amb = make_float2(a.x-b.x, a.y-b.y);
            float cw, sw; __sincosf(th0 * (float)p, &sw, &cw);
            float2 t = make_float2(amb.x*cw - amb.y*sw, amb.x*sw + amb.y*cw);
            y[q + s*(2*p)  ] = apb;
            y[q + s*(2*p+1)] = t;
        }
        __syncthreads();
        float2* tt = src; src = dst; dst = tt;
        n >>= 1; s <<= 1;
    }
}

// ------------------------- forward: row pass (4 rows/block) ------------------
__global__ void k_fwd_row(const float* __restrict__ x)
{
    __shared__ float2 s0[4*N384], s1[4*N384];
    int img  = blockIdx.x / 96;
    int tile = blockIdx.x - img*96;
    int r0 = tile * 4;
    int b = img / 3, d = img - b*3;
    int bs = (b + 2) & 3;            // fftshift over batch axis
    int ds = (d + 2) % 3;            // fftshift over channel axis
    const float* xr = x + ((size_t)(bs*3 + ds)*NPIX) + (size_t)r0*N384;
    for (int idx = threadIdx.x; idx < 4*N384; idx += blockDim.x)
        s0[idx] = make_float2(xr[idx], 0.f);
    fft384_multi<4>(s0, s1, threadIdx.x, blockDim.x, -1.f);
    float2* out = g_A + (size_t)img*NPIX + (size_t)r0*N384;
    for (int idx = threadIdx.x; idx < 4*N384; idx += blockDim.x)
        out[idx] = s0[idx];
}

// ------------------------- forward: column pass (+h,w shift) -----------------
__global__ void k_fwd_col()
{
    __shared__ float2 s0[4*N384], s1[4*N384];
    int img  = blockIdx.x / 96;
    int tile = blockIdx.x - img*96;
    int c0 = tile * 4;
    const float2* A = g_A + (size_t)img*NPIX;
    for (int idx = threadIdx.x; idx < 4*N384; idx += blockDim.x) {
        int h = idx >> 2, c = idx & 3;
        s0[c*N384 + h] = A[h*N384 + c0 + c];
    }
    fft384_multi<4>(s0, s1, threadIdx.x, blockDim.x, -1.f);
    float2* Xs = g_Xs + (size_t)img*NPIX;
    for (int idx = threadIdx.x; idx < 4*N384; idx += blockDim.x) {
        int hh = idx >> 2, c = idx & 3;
        int h2 = hh + 192; if (h2 >= N384) h2 -= N384;
        int w2 = c0 + c + 192; if (w2 >= N384) w2 -= N384;
        Xs[h2*N384 + w2] = s0[c*N384 + hh];
    }
}

// ---------------- attention MLP + log-Gabor bank + attended ------------------
__global__ void k_attn(const float* __restrict__ theta, const float* __restrict__ sigma,
                       const float* __restrict__ f0,    const float* __restrict__ theta0,
                       const float* __restrict__ w1,    const float* __restrict__ b1,
                       const float* __restrict__ w2,    const float* __restrict__ b2)
{
    __shared__ float sw1[192], sb1[64], sw2[576], sb2[9];
    __shared__ float sth[27], slf0[27], sc1[27], sc2[27];
    __shared__ int s_uni;
    int tid = threadIdx.x;
    for (int i = tid; i < 192; i += 256) sw1[i] = w1[i];
    for (int i = tid; i < 576; i += 256) sw2[i] = w2[i];
    if (tid < 64) sb1[tid] = b1[tid];
    if (tid < 9)  sb2[tid] = b2[tid];
    if (tid < 27) {
        sth[tid]  = theta[tid];
        float ls  = __logf(sigma[tid]);
        sc1[tid]  = -0.5f / (ls*ls);
        float t0  = theta0[tid];
        sc2[tid]  = -0.5f / (t0*t0);
        slf0[tid] = __logf(f0[tid]);
    }
    __syncthreads();
    if (tid == 0) {
        int u = 1;
        #pragma unroll
        for (int i = 1; i < 27; i++) if (slf0[i] != slf0[0]) u = 0;
        s_uni = u;
    }
    __syncthreads();
    const int uni = s_uni;

    int p = blockIdx.x*256 + tid;
    int h = p / N384, w = p - h*N384;
    float yy = -1.f + (2.f/383.f) * (float)h;
    float xx = -1.f + (2.f/383.f) * (float)w;
    float r   = sqrtf(xx*xx + yy*yy + 1e-6f);
    float phi = atan2f(yy, xx);

    float filt[27];
    if (uni) {
        float lr = __logf(r - slf0[0]);
        float lr2 = lr*lr;
        #pragma unroll
        for (int i = 0; i < 27; i++) {
            float dph = phi - sth[i];
            filt[i] = __expf(fmaf(lr2, sc1[i], dph*dph*sc2[i]));
        }
    } else {
        #pragma unroll
        for (int i = 0; i < 27; i++) {
            float lr = __logf(r - slf0[i]);
            float dph = phi - sth[i];
            filt[i] = __expf(fmaf(lr*lr, sc1[i], dph*dph*sc2[i]));
        }
    }

    for (int b = 0; b < 4; b++) {
        float2 X[3]; float mag[3];
        #pragma unroll
        for (int d = 0; d < 3; d++) {
            X[d] = g_Xs[(size_t)(b*3+d)*NPIX + p];
            mag[d] = sqrtf(X[d].x*X[d].x + X[d].y*X[d].y);
        }
        float logit[9];
        #pragma unroll
        for (int o = 0; o < 9; o++) logit[o] = sb2[o];
        for (int j = 0; j < 64; j++) {
            float t = sb1[j] + sw1[j*3]*mag[0] + sw1[j*3+1]*mag[1] + sw1[j*3+2]*mag[2];
            t = fmaxf(t, 0.f);
            #pragma unroll
            for (int o = 0; o < 9; o++) logit[o] = fmaf(sw2[o*64+j], t, logit[o]);
        }
        float mx = logit[0];
        #pragma unroll
        for (int o = 1; o < 9; o++) mx = fmaxf(mx, logit[o]);
        float att[9], ssum = 0.f;
        #pragma unroll
        for (int o = 0; o < 9; o++) { att[o] = __expf(logit[o]-mx); ssum += att[o]; }
        float inv = __fdividef(1.f, ssum);
        float wg0=0.f, wg1=0.f, wg2=0.f;
        #pragma unroll
        for (int sc = 0; sc < 9; sc++) {
            float a = att[sc] * inv;
            wg0 = fmaf(a, filt[sc*3+0], wg0);
            wg1 = fmaf(a, filt[sc*3+1], wg1);
            wg2 = fmaf(a, filt[sc*3+2], wg2);
        }
        float2 acc;
        acc.x = X[0].x*wg0 + X[1].x*wg1 + X[2].x*wg2;
        acc.y = X[0].y*wg0 + X[1].y*wg1 + X[2].y*wg2;
        g_Att[(size_t)b*NPIX + p] = acc;
    }
}

// ---------------- inverse: column pass with band mask (pruned) ---------------
__global__ void k_inv_col(const float* __restrict__ band)
{
    __shared__ float2 s0[4*N384], s1[4*N384];
    int plane = blockIdx.x / 96;
    int tile  = blockIdx.x - plane*96;
    int kap  = plane / 12;
    int rest = plane - kap*12;
    int del  = rest / 4;
    int beta = rest - del*4;
    float b0 = band[(kap*3+del)*2+0], b1 = band[(kap*3+del)*2+1];
    int si = (int)floorf((b0+1.f)*0.5f*384.f);
    int ei = (int)floorf((b1+1.f)*0.5f*384.f);
    int c0 = tile * 4;
    // prune: empty plane or tile fully outside the column band
    if (si >= ei || c0 >= ei || c0+4 <= si) return;

    const float2* At = g_Att + (size_t)beta*NPIX;
    for (int idx = threadIdx.x; idx < 4*N384; idx += blockDim.x) {
        int h = idx >> 2, c = idx & 3;
        int wc = c0 + c;
        float2 v = make_float2(0.f, 0.f);
        if (wc >= si && wc < ei && h >= si && h < ei)
            v = At[h*N384 + wc];
        s0[c*N384 + h] = v;
    }
    fft384_multi<4>(s0, s1, threadIdx.x, blockDim.x, +1.f);
    float2* T = g_Tmp + (size_t)plane*NPIX;
    const float sc = 1.f/384.f;
    for (int idx = threadIdx.x; idx < 4*N384; idx += blockDim.x) {
        int n = idx >> 2, c = idx & 3;
        int wc = c0 + c;
        if (wc >= si && wc < ei) {
            float2 v = s0[c*N384 + n];
            T[n*N384 + wc] = make_float2(v.x*sc, v.y*sc);
        }
    }
}

// ------- inverse row pass fused with final mix/assembly (4 rows/block) -------
__global__ void k_inv_rowout(const float* __restrict__ band,
                             const float* __restrict__ mixing,
                             float* __restrict__ out)
{
    __shared__ float2 s0[4*N384], s1[4*N384];
    int plane = blockIdx.x / 96;
    int tile  = blockIdx.x - plane*96;
    int n0 = tile * 4;
    int kap  = plane / 12;
    int rest = plane - kap*12;
    int del  = rest / 4;
    int beta = rest - del*4;
    int co = (kap + 2) % 3;
    int ci = (del + 2) % 3;
    int b  = (beta + 2) & 3;
    float b0 = band[(kap*3+del)*2+0], b1 = band[(kap*3+del)*2+1];
    int si = (int)floorf((b0+1.f)*0.5f*384.f);
    int ei = (int)floorf((b1+1.f)*0.5f*384.f);
    float mix = mixing[0];
    float om  = 1.f - mix;
    const float* cv = g_Cv + (size_t)(b*3+ci)*NPIX + (size_t)n0*N384;
    float* ob = out + (size_t)(co*12 + b*3 + ci)*NPIX + (size_t)n0*N384;

    if (si >= ei) {  // plane is all-zero in frequency domain -> P == 0
        for (int idx = threadIdx.x; idx < 4*N384; idx += blockDim.x) {
            float v = om * cv[idx];
            ob[idx]            = v;
            ob[36*NPIX + idx]  = v;
            ob[72*NPIX + idx]  = v;
            ob[108*NPIX + idx] = v;
        }
        return;
    }

    const float2* T = g_Tmp + (size_t)plane*NPIX + (size_t)n0*N384;
    for (int idx = threadIdx.x; idx < 4*N384; idx += blockDim.x) {
        int c = idx / 384;
        int w = idx - c*384;          // 384 is NOT a power of two: no & trick
        float2 v = make_float2(0.f, 0.f);
        if (w >= si && w < ei) v = T[idx];
        s0[idx] = v;
    }
    fft384_multi<4>(s0, s1, threadIdx.x, blockDim.x, +1.f);
    const float sc = 1.f/384.f;
    for (int idx = threadIdx.x; idx < 4*N384; idx += blockDim.x) {
        int c = idx / 384, w = idx - c*384;
        int n = n0 + c;
        float v = s0[idx].x * sc;
        if ((n + w) & 1) v = -v;
        float o = fmaf(mix, v, om * cv[idx]);
        ob[idx]            = o;
        ob[36*NPIX + idx]  = o;
        ob[72*NPIX + idx]  = o;
        ob[108*NPIX + idx] = o;
    }
}

// ---------------- spatial 3x3 conv -------------------------------------------
__global__ void k_conv(const float* __restrict__ x, const float* __restrict__ cw)
{
    int t = blockIdx.x*256 + threadIdx.x;
    if (t >= 12*NPIX) return;
    int w = t % N384;
    int h = (t / N384) % N384;
    int o = (t / NPIX) % 3;
    int b = t / (3*NPIX);
    float acc = 0.f;
    #pragma unroll
    for (int i = 0; i < 3; i++) {
        const float* xp = x + (size_t)(b*3+i)*NPIX;
        #pragma unroll
        for (int kh = 0; kh < 3; kh++) {
            int hh = h + kh - 1;
            if (hh < 0 || hh >= N384) continue;
            #pragma unroll
            for (int kw = 0; kw < 3; kw++) {
                int ww = w + kw - 1;
                if (ww < 0 || ww >= N384) continue;
                acc = fmaf(xp[hh*N384+ww], cw[((o*3+i)*3+kh)*3+kw], acc);
            }
        }
    }
    g_Cv[t] = acc;
}

// ------------------------------------------------------------------
extern "C" void kernel_launch(void* const* d_in, const int* in_sizes, int n_in,
                              void* d_out, int out_size)
{
    const float* x      = (const float*)d_in[0];
    const float* theta  = (const float*)d_in[1];
    const float* sigma  = (const float*)d_in[2];
    const float* f0     = (const float*)d_in[3];
    const float* theta0 = (const float*)d_in[4];
    const float* aw1    = (const float*)d_in[5];
    const float* ab1    = (const float*)d_in[6];
    const float* aw2    = (const float*)d_in[7];
    const float* ab2    = (const float*)d_in[8];
    const float* convw  = (const float*)d_in[9];
    const float* mixing = (const float*)d_in[10];
    const float* band   = (const float*)d_in[11];
    float* out = (float*)d_out;

    k_fwd_row<<<12*96, 256>>>(x);
    k_fwd_col<<<12*96, 256>>>();
    k_attn<<<NPIX/256, 256>>>(theta, sigma, f0, theta0, aw1, ab1, aw2, ab2);
    k_conv<<<(12*NPIX+255)/256, 256>>>(x, convw);
    k_inv_col<<<36*96, 256>>>(band);
    k_inv_rowout<<<36*96, 256>>>(band, mixing, out);
}

// round 4
// speedup vs baseline: 1.9471x; 1.3338x over previous
#include <cuda_runtime.h>
#include <cuda_bf16.h>
#include <math.h>

#define N384 384
#define NPIX (384*384)
#define PI_F 3.14159265358979323846f

// -------- scratch (static __device__ arrays; allocation is forbidden) --------
__device__ float2 g_A  [12*NPIX];   // forward row-pass result
__device__ float2 g_Xs [12*NPIX];   // shifted spectrum  [b*3+d][h][w]
__device__ float2 g_Att[ 4*NPIX];   // attended (shifted coords)
__device__ float2 g_Tmp[36*NPIX];   // inverse column-pass result (band cols only valid)
__device__ float  g_Cv [12*NPIX];   // spatial conv  [b][o][h][w]

__device__ __forceinline__ float2 cmul(float2 a, float2 b) {
    return make_float2(a.x*b.x - a.y*b.y, a.x*b.y + a.y*b.x);
}

// ---------------- 384-pt Stockham FFT (radix-3 then 7x radix-2) --------------
template<int NC>
__device__ void fft384_multi(float2* s0, float2* s1, int tid, int nt, float dir)
{
    __syncthreads();
    {
        const float th0 = dir * (2.0f * PI_F / 384.0f);
        const float s3  = dir * 0.8660254037844386f;
        const int total = NC * 128;
        for (int idx = tid; idx < total; idx += nt) {
            int c = idx >> 7;
            int p = idx & 127;
            const float2* x = s0 + c*N384;
            float2*       y = s1 + c*N384;
            float2 a = x[p], b = x[p+128], cc = x[p+256];
            float t1x = b.x+cc.x, t1y = b.y+cc.y;
            float t2x = b.x-cc.x, t2y = b.y-cc.y;
            float2 x0 = make_float2(a.x+t1x, a.y+t1y);
            float ux = a.x - 0.5f*t1x, uy = a.y - 0.5f*t1y;
            float vx = -s3*t2y,        vy =  s3*t2x;
            float2 x1 = make_float2(ux+vx, uy+vy);
            float2 x2 = make_float2(ux-vx, uy-vy);
            float cw, sw; __sincosf(th0 * (float)p, &sw, &cw);
            float2 w1 = make_float2(cw, sw);
            float2 w2 = cmul(w1, w1);
            y[3*p  ] = x0;
            y[3*p+1] = cmul(x1, w1);
            y[3*p+2] = cmul(x2, w2);
        }
        __syncthreads();
    }
    int n = 128, s = 3;
    float2 *src = s1, *dst = s0;
    for (int st = 0; st < 7; st++) {
        int m = n >> 1;
        float th0 = dir * (2.0f * PI_F / (float)n);
        const int total = NC * 192;
        for (int idx = tid; idx < total; idx += nt) {
            int c = idx / 192;
            int r = idx - c*192;
            int p = r / s, q = r - p*s;
            const float2* x = src + c*N384;
            float2*       y = dst + c*N384;
            float2 a = x[q + s*p], b = x[q + s*(p+m)];
            float2 apb = make_float2(a.x+b.x, a.y+b.y);
            float2 amb = make_float2(a.x-b.x, a.y-b.y);
            float cw, sw; __sincosf(th0 * (float)p, &sw, &cw);
            float2 t = make_float2(amb.x*cw - amb.y*sw, amb.x*sw + amb.y*cw);
            y[q + s*(2*p)  ] = apb;
            y[q + s*(2*p+1)] = t;
        }
        __syncthreads();
        float2* tt = src; src = dst; dst = tt;
        n >>= 1; s <<= 1;
    }
}

// ------------------------- forward: row pass (4 rows/block) ------------------
__global__ void k_fwd_row(const float* __restrict__ x)
{
    __shared__ float2 s0[4*N384], s1[4*N384];
    int img  = blockIdx.x / 96;
    int tile = blockIdx.x - img*96;
    int r0 = tile * 4;
    int b = img / 3, d = img - b*3;
    int bs = (b + 2) & 3;
    int ds = (d + 2) % 3;
    const float* xr = x + ((size_t)(bs*3 + ds)*NPIX) + (size_t)r0*N384;
    for (int idx = threadIdx.x; idx < 4*N384; idx += blockDim.x)
        s0[idx] = make_float2(xr[idx], 0.f);
    fft384_multi<4>(s0, s1, threadIdx.x, blockDim.x, -1.f);
    float2* out = g_A + (size_t)img*NPIX + (size_t)r0*N384;
    for (int idx = threadIdx.x; idx < 4*N384; idx += blockDim.x)
        out[idx] = s0[idx];
}

// ------------------------- forward: column pass (+h,w shift) -----------------
__global__ void k_fwd_col()
{
    __shared__ float2 s0[4*N384], s1[4*N384];
    int img  = blockIdx.x / 96;
    int tile = blockIdx.x - img*96;
    int c0 = tile * 4;
    const float2* A = g_A + (size_t)img*NPIX;
    for (int idx = threadIdx.x; idx < 4*N384; idx += blockDim.x) {
        int h = idx >> 2, c = idx & 3;
        s0[c*N384 + h] = A[h*N384 + c0 + c];
    }
    fft384_multi<4>(s0, s1, threadIdx.x, blockDim.x, -1.f);
    float2* Xs = g_Xs + (size_t)img*NPIX;
    for (int idx = threadIdx.x; idx < 4*N384; idx += blockDim.x) {
        int hh = idx >> 2, c = idx & 3;
        int h2 = hh + 192; if (h2 >= N384) h2 -= N384;
        int w2 = c0 + c + 192; if (w2 >= N384) w2 -= N384;
        Xs[h2*N384 + w2] = s0[c*N384 + hh];
    }
}

// ---------------- attention MLP + log-Gabor bank + attended ------------------
__global__ void __launch_bounds__(256)
k_attn(const float* __restrict__ theta, const float* __restrict__ sigma,
       const float* __restrict__ f0,    const float* __restrict__ theta0,
       const float* __restrict__ w1,    const float* __restrict__ b1,
       const float* __restrict__ w2,    const float* __restrict__ b2)
{
    __shared__ float sw1[192], sb1[64], sw2[576], sb2[9];
    __shared__ float sth[27], slf0[27], sc1[27], sc2[27];
    __shared__ int s_uni;
    int tid = threadIdx.x;
    for (int i = tid; i < 192; i += 256) sw1[i] = w1[i];
    for (int i = tid; i < 576; i += 256) sw2[i] = w2[i];
    if (tid < 64) sb1[tid] = b1[tid];
    if (tid < 9)  sb2[tid] = b2[tid];
    if (tid < 27) {
        sth[tid]  = theta[tid];
        float ls  = __logf(sigma[tid]);
        sc1[tid]  = -0.5f / (ls*ls);
        float t0  = theta0[tid];
        sc2[tid]  = -0.5f / (t0*t0);
        slf0[tid] = __logf(f0[tid]);
    }
    __syncthreads();
    if (tid == 0) {
        int u = 1;
        #pragma unroll
        for (int i = 1; i < 27; i++) if (slf0[i] != slf0[0]) u = 0;
        s_uni = u;
    }
    __syncthreads();
    const int uni = s_uni;

    int p = blockIdx.x*256 + tid;

    // magnitudes for all 4 batches (12 loads)
    float mag[12];
    #pragma unroll
    for (int i = 0; i < 12; i++) {
        float2 X = g_Xs[(size_t)i*NPIX + p];
        mag[i] = sqrtf(X.x*X.x + X.y*X.y);
    }

    // MLP for all 4 batches in one j-loop: 13 LDS + 48 FMA per j
    float logit[36];
    #pragma unroll
    for (int b = 0; b < 4; b++)
        #pragma unroll
        for (int o = 0; o < 9; o++) logit[b*9+o] = sb2[o];
    for (int j = 0; j < 64; j++) {
        float a0 = sw1[j*3], a1 = sw1[j*3+1], a2 = sw1[j*3+2], bb = sb1[j];
        float t0 = fmaxf(fmaf(a2, mag[2],  fmaf(a1, mag[1],  fmaf(a0, mag[0],  bb))), 0.f);
        float t1 = fmaxf(fmaf(a2, mag[5],  fmaf(a1, mag[4],  fmaf(a0, mag[3],  bb))), 0.f);
        float t2 = fmaxf(fmaf(a2, mag[8],  fmaf(a1, mag[7],  fmaf(a0, mag[6],  bb))), 0.f);
        float t3 = fmaxf(fmaf(a2, mag[11], fmaf(a1, mag[10], fmaf(a0, mag[9],  bb))), 0.f);
        #pragma unroll
        for (int o = 0; o < 9; o++) {
            float wv = sw2[o*64+j];
            logit[o]    = fmaf(wv, t0, logit[o]);
            logit[9+o]  = fmaf(wv, t1, logit[9+o]);
            logit[18+o] = fmaf(wv, t2, logit[18+o]);
            logit[27+o] = fmaf(wv, t3, logit[27+o]);
        }
    }

    // log-Gabor filter bank
    int h = p / N384, w = p - h*N384;
    float yy = -1.f + (2.f/383.f) * (float)h;
    float xx = -1.f + (2.f/383.f) * (float)w;
    float r   = sqrtf(xx*xx + yy*yy + 1e-6f);
    float phi = atan2f(yy, xx);
    float filt[27];
    if (uni) {
        float lr = __logf(r - slf0[0]);
        float lr2 = lr*lr;
        #pragma unroll
        for (int i = 0; i < 27; i++) {
            float dph = phi - sth[i];
            filt[i] = __expf(fmaf(lr2, sc1[i], dph*dph*sc2[i]));
        }
    } else {
        #pragma unroll
        for (int i = 0; i < 27; i++) {
            float lr = __logf(r - slf0[i]);
            float dph = phi - sth[i];
            filt[i] = __expf(fmaf(lr*lr, sc1[i], dph*dph*sc2[i]));
        }
    }

    // softmax + weighted filter + apply to spectrum, per batch
    #pragma unroll
    for (int b = 0; b < 4; b++) {
        float* lg = logit + b*9;
        float mx = lg[0];
        #pragma unroll
        for (int o = 1; o < 9; o++) mx = fmaxf(mx, lg[o]);
        float att[9], ssum = 0.f;
        #pragma unroll
        for (int o = 0; o < 9; o++) { att[o] = __expf(lg[o]-mx); ssum += att[o]; }
        float inv = __fdividef(1.f, ssum);
        float wg0=0.f, wg1=0.f, wg2=0.f;
        #pragma unroll
        for (int sc = 0; sc < 9; sc++) {
            float a = att[sc] * inv;
            wg0 = fmaf(a, filt[sc*3+0], wg0);
            wg1 = fmaf(a, filt[sc*3+1], wg1);
            wg2 = fmaf(a, filt[sc*3+2], wg2);
        }
        float2 X0 = g_Xs[(size_t)(b*3+0)*NPIX + p];
        float2 X1 = g_Xs[(size_t)(b*3+1)*NPIX + p];
        float2 X2 = g_Xs[(size_t)(b*3+2)*NPIX + p];
        float2 acc;
        acc.x = X0.x*wg0 + X1.x*wg1 + X2.x*wg2;
        acc.y = X0.y*wg0 + X1.y*wg1 + X2.y*wg2;
        g_Att[(size_t)b*NPIX + p] = acc;
    }
}

// ---------------- inverse: column pass with band mask (pruned) ---------------
__global__ void k_inv_col(const float* __restrict__ band)
{
    __shared__ float2 s0[4*N384], s1[4*N384];
    int plane = blockIdx.x / 96;
    int tile  = blockIdx.x - plane*96;
    int kap  = plane / 12;
    int rest = plane - kap*12;
    int del  = rest / 4;
    int beta = rest - del*4;
    float b0 = band[(kap*3+del)*2+0], b1 = band[(kap*3+del)*2+1];
    int si = (int)floorf((b0+1.f)*0.5f*384.f);
    int ei = (int)floorf((b1+1.f)*0.5f*384.f);
    int c0 = tile * 4;
    if (si >= ei || c0 >= ei || c0+4 <= si) return;

    const float2* At = g_Att + (size_t)beta*NPIX;
    for (int idx = threadIdx.x; idx < 4*N384; idx += blockDim.x) {
        int h = idx >> 2, c = idx & 3;
        int wc = c0 + c;
        float2 v = make_float2(0.f, 0.f);
        if (wc >= si && wc < ei && h >= si && h < ei)
            v = At[h*N384 + wc];
        s0[c*N384 + h] = v;
    }
    fft384_multi<4>(s0, s1, threadIdx.x, blockDim.x, +1.f);
    float2* T = g_Tmp + (size_t)plane*NPIX;
    const float sc = 1.f/384.f;
    for (int idx = threadIdx.x; idx < 4*N384; idx += blockDim.x) {
        int n = idx >> 2, c = idx & 3;
        int wc = c0 + c;
        if (wc >= si && wc < ei) {
            float2 v = s0[c*N384 + n];
            T[n*N384 + wc] = make_float2(v.x*sc, v.y*sc);
        }
    }
}

// ------- inverse row pass fused with final mix/assembly (4 rows/block) -------
__global__ void k_inv_rowout(const float* __restrict__ band,
                             const float* __restrict__ mixing,
                             float* __restrict__ out)
{
    __shared__ float2 s0[4*N384], s1[4*N384];
    int plane = blockIdx.x / 96;
    int tile  = blockIdx.x - plane*96;
    int n0 = tile * 4;
    int kap  = plane / 12;
    int rest = plane - kap*12;
    int del  = rest / 4;
    int beta = rest - del*4;
    int co = (kap + 2) % 3;
    int ci = (del + 2) % 3;
    int b  = (beta + 2) & 3;
    float b0 = band[(kap*3+del)*2+0], b1 = band[(kap*3+del)*2+1];
    int si = (int)floorf((b0+1.f)*0.5f*384.f);
    int ei = (int)floorf((b1+1.f)*0.5f*384.f);
    float mix = mixing[0];
    float om  = 1.f - mix;
    const float* cv = g_Cv + (size_t)(b*3+ci)*NPIX + (size_t)n0*N384;
    float* ob = out + (size_t)(co*12 + b*3 + ci)*NPIX + (size_t)n0*N384;

    if (si >= ei) {
        for (int idx = threadIdx.x; idx < 4*N384; idx += blockDim.x) {
            float v = om * cv[idx];
            ob[idx]            = v;
            ob[36*NPIX + idx]  = v;
            ob[72*NPIX + idx]  = v;
            ob[108*NPIX + idx] = v;
        }
        return;
    }

    const float2* T = g_Tmp + (size_t)plane*NPIX + (size_t)n0*N384;
    for (int idx = threadIdx.x; idx < 4*N384; idx += blockDim.x) {
        int c = idx / 384;
        int w = idx - c*384;
        float2 v = make_float2(0.f, 0.f);
        if (w >= si && w < ei) v = T[idx];
        s0[idx] = v;
    }
    fft384_multi<4>(s0, s1, threadIdx.x, blockDim.x, +1.f);
    const float sc = 1.f/384.f;
    for (int idx = threadIdx.x; idx < 4*N384; idx += blockDim.x) {
        int c = idx / 384, w = idx - c*384;
        int n = n0 + c;
        float v = s0[idx].x * sc;
        if ((n + w) & 1) v = -v;
        float o = fmaf(mix, v, om * cv[idx]);
        ob[idx]            = o;
        ob[36*NPIX + idx]  = o;
        ob[72*NPIX + idx]  = o;
        ob[108*NPIX + idx] = o;
    }
}

// ---------------- spatial 3x3 conv: 3 outputs per thread ---------------------
__global__ void __launch_bounds__(256)
k_conv(const float* __restrict__ x, const float* __restrict__ cw)
{
    __shared__ float scw[81];            // [o][i][kh][kw]
    if (threadIdx.x < 81) scw[threadIdx.x] = cw[threadIdx.x];
    __syncthreads();

    int t = blockIdx.x*256 + threadIdx.x;   // 4*NPIX threads exactly
    int b = t / NPIX;
    int p = t - b*NPIX;
    int h = p / N384, w = p - h*N384;

    float acc0 = 0.f, acc1 = 0.f, acc2 = 0.f;
    bool hlo = (h > 0), hhi = (h < 383);
    bool wlo = (w > 0), whi = (w < 383);

    #pragma unroll
    for (int i = 0; i < 3; i++) {
        const float* xp = x + (size_t)(b*3+i)*NPIX + p;   // center
        float v[9];
        v[0] = (hlo && wlo) ? xp[-N384-1] : 0.f;
        v[1] = (hlo       ) ? xp[-N384  ] : 0.f;
        v[2] = (hlo && whi) ? xp[-N384+1] : 0.f;
        v[3] = (       wlo) ? xp[-1]      : 0.f;
        v[4] =                xp[0];
        v[5] = (       whi) ? xp[1]       : 0.f;
        v[6] = (hhi && wlo) ? xp[N384-1]  : 0.f;
        v[7] = (hhi       ) ? xp[N384]    : 0.f;
        v[8] = (hhi && whi) ? xp[N384+1]  : 0.f;
        const float* w0 = scw + (0*3+i)*9;
        const float* w1 = scw + (1*3+i)*9;
        const float* w2 = scw + (2*3+i)*9;
        #pragma unroll
        for (int k = 0; k < 9; k++) {
            acc0 = fmaf(v[k], w0[k], acc0);
            acc1 = fmaf(v[k], w1[k], acc1);
            acc2 = fmaf(v[k], w2[k], acc2);
        }
    }
    g_Cv[(size_t)(b*3+0)*NPIX + p] = acc0;
    g_Cv[(size_t)(b*3+1)*NPIX + p] = acc1;
    g_Cv[(size_t)(b*3+2)*NPIX + p] = acc2;
}

// ------------------------------------------------------------------
extern "C" void kernel_launch(void* const* d_in, const int* in_sizes, int n_in,
                              void* d_out, int out_size)
{
    const float* x      = (const float*)d_in[0];
    const float* theta  = (const float*)d_in[1];
    const float* sigma  = (const float*)d_in[2];
    const float* f0     = (const float*)d_in[3];
    const float* theta0 = (const float*)d_in[4];
    const float* aw1    = (const float*)d_in[5];
    const float* ab1    = (const float*)d_in[6];
    const float* aw2    = (const float*)d_in[7];
    const float* ab2    = (const float*)d_in[8];
    const float* convw  = (const float*)d_in[9];
    const float* mixing = (const float*)d_in[10];
    const float* band   = (const float*)d_in[11];
    float* out = (float*)d_out;

    k_fwd_row<<<12*96, 256>>>(x);
    k_fwd_col<<<12*96, 256>>>();
    k_attn<<<NPIX/256, 256>>>(theta, sigma, f0, theta0, aw1, ab1, aw2, ab2);
    k_conv<<<4*NPIX/256, 256>>>(x, convw);
    k_inv_col<<<36*96, 256>>>(band);
    k_inv_rowout<<<36*96, 256>>>(band, mixing, out);
}

// round 5
// speedup vs baseline: 2.3365x; 1.2000x over previous
#include <cuda_runtime.h>
#include <cuda_bf16.h>
#include <math.h>

#define N384 384
#define NPIX (384*384)
#define PI_F 3.14159265358979323846f

// -------- scratch (static __device__ arrays; allocation is forbidden) --------
__device__ float2 g_A  [12*NPIX];   // forward row-pass result
__device__ float2 g_Xs [12*NPIX];   // shifted spectrum  [b*3+d][h][w]
__device__ float2 g_Att[ 4*NPIX];   // attended (shifted coords)
__device__ float2 g_Tmp[36*NPIX];   // inverse column-pass result (band cols only valid)
__device__ float  g_Cv [12*NPIX];   // spatial conv  [b][o][h][w]

__device__ __forceinline__ float2 cmul(float2 a, float2 b) {
    return make_float2(a.x*b.x - a.y*b.y, a.x*b.y + a.y*b.x);
}

// ---------------- 384-pt Stockham FFT (radix-3 then 7x radix-2) --------------
template<int NC>
__device__ void fft384_multi(float2* s0, float2* s1, int tid, int nt, float dir)
{
    __syncthreads();
    {
        const float th0 = dir * (2.0f * PI_F / 384.0f);
        const float s3  = dir * 0.8660254037844386f;
        const int total = NC * 128;
        for (int idx = tid; idx < total; idx += nt) {
            int c = idx >> 7;
            int p = idx & 127;
            const float2* x = s0 + c*N384;
            float2*       y = s1 + c*N384;
            float2 a = x[p], b = x[p+128], cc = x[p+256];
            float t1x = b.x+cc.x, t1y = b.y+cc.y;
            float t2x = b.x-cc.x, t2y = b.y-cc.y;
            float2 x0 = make_float2(a.x+t1x, a.y+t1y);
            float ux = a.x - 0.5f*t1x, uy = a.y - 0.5f*t1y;
            float vx = -s3*t2y,        vy =  s3*t2x;
            float2 x1 = make_float2(ux+vx, uy+vy);
            float2 x2 = make_float2(ux-vx, uy-vy);
            float cw, sw; __sincosf(th0 * (float)p, &sw, &cw);
            float2 w1 = make_float2(cw, sw);
            float2 w2 = cmul(w1, w1);
            y[3*p  ] = x0;
            y[3*p+1] = cmul(x1, w1);
            y[3*p+2] = cmul(x2, w2);
        }
        __syncthreads();
    }
    int n = 128, s = 3;
    float2 *src = s1, *dst = s0;
    for (int st = 0; st < 7; st++) {
        int m = n >> 1;
        float th0 = dir * (2.0f * PI_F / (float)n);
        const int total = NC * 192;
        for (int idx = tid; idx < total; idx += nt) {
            int c = idx / 192;
            int r = idx - c*192;
            int p = r / s, q = r - p*s;
            const float2* x = src + c*N384;
            float2*       y = dst + c*N384;
            float2 a = x[q + s*p], b = x[q + s*(p+m)];
            float2 apb = make_float2(a.x+b.x, a.y+b.y);
            float2 amb = make_float2(a.x-b.x, a.y-b.y);
            float cw, sw; __sincosf(th0 * (float)p, &sw, &cw);
            float2 t = make_float2(amb.x*cw - amb.y*sw, amb.x*sw + amb.y*cw);
            y[q + s*(2*p)  ] = apb;
            y[q + s*(2*p+1)] = t;
        }
        __syncthreads();
        float2* tt = src; src = dst; dst = tt;
        n >>= 1; s <<= 1;
    }
}

// -------- forward row pass: real-input packing, 8 rows (4 packed FFTs)/block --
__global__ void k_fwd_row(const float* __restrict__ x)
{
    __shared__ float2 s0[4*N384], s1[4*N384];
    int img  = blockIdx.x / 48;
    int tile = blockIdx.x - img*48;
    int r0 = tile * 8;
    int b = img / 3, d = img - b*3;
    int bs = (b + 2) & 3;
    int ds = (d + 2) % 3;
    const float* xr = x + ((size_t)(bs*3 + ds)*NPIX) + (size_t)r0*N384;
    for (int idx = threadIdx.x; idx < 4*N384; idx += blockDim.x) {
        int c = idx / N384, w = idx - c*N384;
        s0[idx] = make_float2(xr[(2*c)*N384 + w], xr[(2*c+1)*N384 + w]);
    }
    fft384_multi<4>(s0, s1, threadIdx.x, blockDim.x, -1.f);
    float2* out = g_A + (size_t)img*NPIX + (size_t)r0*N384;
    for (int idx = threadIdx.x; idx < 4*N384; idx += blockDim.x) {
        int c = idx / N384, w = idx - c*N384;
        int mw = (w == 0) ? 0 : (N384 - w);
        float2 F1 = s0[c*N384 + w];
        float2 F2 = s0[c*N384 + mw];          // conj taken below
        float2 ev = make_float2(0.5f*(F1.x + F2.x), 0.5f*(F1.y - F2.y));
        float dx = F1.x - F2.x, dy = F1.y + F2.y;
        float2 od = make_float2(0.5f*dy, -0.5f*dx);
        out[(2*c)*N384 + w]   = ev;
        out[(2*c+1)*N384 + w] = od;
    }
}

// -------- forward column pass: Hermitian halving (+h,w shift) ----------------
__global__ void k_fwd_col()
{
    __shared__ float2 s0[4*N384], s1[4*N384];
    int img  = blockIdx.x / 49;
    int tile = blockIdx.x - img*49;
    int c0 = tile * 4;                      // columns 0..195 computed
    const float2* A = g_A + (size_t)img*NPIX;
    for (int idx = threadIdx.x; idx < 4*N384; idx += blockDim.x) {
        int h = idx >> 2, c = idx & 3;
        s0[c*N384 + h] = A[h*N384 + c0 + c];
    }
    fft384_multi<4>(s0, s1, threadIdx.x, blockDim.x, -1.f);
    float2* Xs = g_Xs + (size_t)img*NPIX;
    for (int idx = threadIdx.x; idx < 4*N384; idx += blockDim.x) {
        int hh = idx >> 2, c = idx & 3;
        int l = c0 + c;
        float2 v = s0[c*N384 + hh];
        if (l <= 192) {
            int h2 = hh + 192; if (h2 >= N384) h2 -= N384;
            int w2 = l + 192;  if (w2 >= N384) w2 -= N384;
            Xs[h2*N384 + w2] = v;
        }
        if (l >= 1 && l <= 191) {
            int hm = ((N384 - hh) % N384) + 192; if (hm >= N384) hm -= N384;
            int wm = 192 - l;                    // (576 - l) % 384 for l in 1..191
            Xs[hm*N384 + wm] = make_float2(v.x, -v.y);
        }
    }
}

// ---------------- attention MLP + log-Gabor bank + attended ------------------
__global__ void __launch_bounds__(256)
k_attn(const float* __restrict__ theta, const float* __restrict__ sigma,
       const float* __restrict__ f0,    const float* __restrict__ theta0,
       const float* __restrict__ w1,    const float* __restrict__ b1,
       const float* __restrict__ w2,    const float* __restrict__ b2)
{
    __shared__ float sw1[192], sb1[64], sw2[576], sb2[9];
    __shared__ float sth[27], slf0[27], sc1[27], sc2[27];
    __shared__ int s_uni;
    int tid = threadIdx.x;
    for (int i = tid; i < 192; i += 256) sw1[i] = w1[i];
    for (int i = tid; i < 576; i += 256) sw2[i] = w2[i];
    if (tid < 64) sb1[tid] = b1[tid];
    if (tid < 9)  sb2[tid] = b2[tid];
    if (tid < 27) {
        sth[tid]  = theta[tid];
        float ls  = __logf(sigma[tid]);
        sc1[tid]  = -0.5f / (ls*ls);
        float t0  = theta0[tid];
        sc2[tid]  = -0.5f / (t0*t0);
        slf0[tid] = __logf(f0[tid]);
    }
    __syncthreads();
    if (tid == 0) {
        int u = 1;
        #pragma unroll
        for (int i = 1; i < 27; i++) if (slf0[i] != slf0[0]) u = 0;
        s_uni = u;
    }
    __syncthreads();
    const int uni = s_uni;

    int p = blockIdx.x*256 + tid;

    float mag[12];
    #pragma unroll
    for (int i = 0; i < 12; i++) {
        float2 X = g_Xs[(size_t)i*NPIX + p];
        mag[i] = sqrtf(X.x*X.x + X.y*X.y);
    }

    float logit[36];
    #pragma unroll
    for (int b = 0; b < 4; b++)
        #pragma unroll
        for (int o = 0; o < 9; o++) logit[b*9+o] = sb2[o];
    for (int j = 0; j < 64; j++) {
        float a0 = sw1[j*3], a1 = sw1[j*3+1], a2 = sw1[j*3+2], bb = sb1[j];
        float t0 = fmaxf(fmaf(a2, mag[2],  fmaf(a1, mag[1],  fmaf(a0, mag[0],  bb))), 0.f);
        float t1 = fmaxf(fmaf(a2, mag[5],  fmaf(a1, mag[4],  fmaf(a0, mag[3],  bb))), 0.f);
        float t2 = fmaxf(fmaf(a2, mag[8],  fmaf(a1, mag[7],  fmaf(a0, mag[6],  bb))), 0.f);
        float t3 = fmaxf(fmaf(a2, mag[11], fmaf(a1, mag[10], fmaf(a0, mag[9],  bb))), 0.f);
        #pragma unroll
        for (int o = 0; o < 9; o++) {
            float wv = sw2[o*64+j];
            logit[o]    = fmaf(wv, t0, logit[o]);
            logit[9+o]  = fmaf(wv, t1, logit[9+o]);
            logit[18+o] = fmaf(wv, t2, logit[18+o]);
            logit[27+o] = fmaf(wv, t3, logit[27+o]);
        }
    }

    int h = p / N384, w = p - h*N384;
    float yy = -1.f + (2.f/383.f) * (float)h;
    float xx = -1.f + (2.f/383.f) * (float)w;
    float r   = sqrtf(xx*xx + yy*yy + 1e-6f);
    float phi = atan2f(yy, xx);
    float filt[27];
    if (uni) {
        float lr = __logf(r - slf0[0]);
        float lr2 = lr*lr;
        #pragma unroll
        for (int i = 0; i < 27; i++) {
            float dph = phi - sth[i];
            filt[i] = __expf(fmaf(lr2, sc1[i], dph*dph*sc2[i]));
        }
    } else {
        #pragma unroll
        for (int i = 0; i < 27; i++) {
            float lr = __logf(r - slf0[i]);
            float dph = phi - sth[i];
            filt[i] = __expf(fmaf(lr*lr, sc1[i], dph*dph*sc2[i]));
        }
    }

    #pragma unroll
    for (int b = 0; b < 4; b++) {
        float* lg = logit + b*9;
        float mx = lg[0];
        #pragma unroll
        for (int o = 1; o < 9; o++) mx = fmaxf(mx, lg[o]);
        float att[9], ssum = 0.f;
        #pragma unroll
        for (int o = 0; o < 9; o++) { att[o] = __expf(lg[o]-mx); ssum += att[o]; }
        float inv = __fdividef(1.f, ssum);
        float wg0=0.f, wg1=0.f, wg2=0.f;
        #pragma unroll
        for (int sc = 0; sc < 9; sc++) {
            float a = att[sc] * inv;
            wg0 = fmaf(a, filt[sc*3+0], wg0);
            wg1 = fmaf(a, filt[sc*3+1], wg1);
            wg2 = fmaf(a, filt[sc*3+2], wg2);
        }
        float2 X0 = g_Xs[(size_t)(b*3+0)*NPIX + p];
        float2 X1 = g_Xs[(size_t)(b*3+1)*NPIX + p];
        float2 X2 = g_Xs[(size_t)(b*3+2)*NPIX + p];
        float2 acc;
        acc.x = X0.x*wg0 + X1.x*wg1 + X2.x*wg2;
        acc.y = X0.y*wg0 + X1.y*wg1 + X2.y*wg2;
        g_Att[(size_t)b*NPIX + p] = acc;
    }
}

// ---------------- inverse: column pass with band mask (pruned) ---------------
__global__ void k_inv_col(const float* __restrict__ band)
{
    __shared__ float2 s0[4*N384], s1[4*N384];
    int plane = blockIdx.x / 96;
    int tile  = blockIdx.x - plane*96;
    int kap  = plane / 12;
    int rest = plane - kap*12;
    int del  = rest / 4;
    int beta = rest - del*4;
    float b0 = band[(kap*3+del)*2+0], b1 = band[(kap*3+del)*2+1];
    int si = (int)floorf((b0+1.f)*0.5f*384.f);
    int ei = (int)floorf((b1+1.f)*0.5f*384.f);
    int c0 = tile * 4;
    if (si >= ei || c0 >= ei || c0+4 <= si) return;

    const float2* At = g_Att + (size_t)beta*NPIX;
    for (int idx = threadIdx.x; idx < 4*N384; idx += blockDim.x) {
        int h = idx >> 2, c = idx & 3;
        int wc = c0 + c;
        float2 v = make_float2(0.f, 0.f);
        if (wc >= si && wc < ei && h >= si && h < ei)
            v = At[h*N384 + wc];
        s0[c*N384 + h] = v;
    }
    fft384_multi<4>(s0, s1, threadIdx.x, blockDim.x, +1.f);
    float2* T = g_Tmp + (size_t)plane*NPIX;
    const float sc = 1.f/384.f;
    for (int idx = threadIdx.x; idx < 4*N384; idx += blockDim.x) {
        int n = idx >> 2, c = idx & 3;
        int wc = c0 + c;
        if (wc >= si && wc < ei) {
            float2 v = s0[c*N384 + n];
            T[n*N384 + wc] = make_float2(v.x*sc, v.y*sc);
        }
    }
}

// -- inverse row pass: Hermitian-packed (2 real rows per FFT) + mix/assembly --
__global__ void k_inv_rowout(const float* __restrict__ band,
                             const float* __restrict__ mixing,
                             float* __restrict__ out)
{
    __shared__ float2 s0[4*N384], s1[4*N384];
    int plane = blockIdx.x / 48;
    int tile  = blockIdx.x - plane*48;
    int n0 = tile * 8;                       // 8 output rows, 4 packed FFTs
    int kap  = plane / 12;
    int rest = plane - kap*12;
    int del  = rest / 4;
    int beta = rest - del*4;
    int co = (kap + 2) % 3;
    int ci = (del + 2) % 3;
    int b  = (beta + 2) & 3;
    float b0 = band[(kap*3+del)*2+0], b1 = band[(kap*3+del)*2+1];
    int si = (int)floorf((b0+1.f)*0.5f*384.f);
    int ei = (int)floorf((b1+1.f)*0.5f*384.f);
    float mix = mixing[0];
    float om  = 1.f - mix;
    const float* cv = g_Cv + (size_t)(b*3+ci)*NPIX + (size_t)n0*N384;
    float* ob = out + (size_t)(co*12 + b*3 + ci)*NPIX + (size_t)n0*N384;

    if (si >= ei) {                           // plane contributes zero
        for (int idx = threadIdx.x; idx < 8*N384; idx += blockDim.x) {
            float v = om * cv[idx];
            ob[idx]            = v;
            ob[36*NPIX + idx]  = v;
            ob[72*NPIX + idx]  = v;
            ob[108*NPIX + idx] = v;
        }
        return;
    }

    // zero, then scatter Hermitian-symmetrized packed rows
    for (int idx = threadIdx.x; idx < 4*N384; idx += blockDim.x)
        s0[idx] = make_float2(0.f, 0.f);
    __syncthreads();
    const float2* Tm = g_Tmp + (size_t)plane*NPIX;
    int K = ei - si;
    for (int j = threadIdx.x; j < 4*K; j += blockDim.x) {
        int c = j & 3;
        int l = si + (j >> 2);
        float2 T1 = Tm[(size_t)(n0 + 2*c)*N384 + l];
        float2 T2 = Tm[(size_t)(n0 + 2*c + 1)*N384 + l];
        float2 zl = make_float2(T1.x - T2.y, T1.y + T2.x);   // T1 + i*T2
        float2 zm = make_float2(T1.x + T2.y, T2.x - T1.y);   // conj(T1) + i*conj(T2)
        int lm = N384 - l;                                   // l in [192,384) -> lm in (0,192]
        if (lm == l) {
            s0[c*N384 + l] = make_float2(zl.x + zm.x, zl.y + zm.y);
        } else {
            s0[c*N384 + l]  = zl;
            s0[c*N384 + lm] = zm;
        }
    }
    fft384_multi<4>(s0, s1, threadIdx.x, blockDim.x, +1.f);
    const float sc = 1.f/768.f;               // 1/(2*384)
    for (int idx = threadIdx.x; idx < 4*N384; idx += blockDim.x) {
        int c = idx / N384, m = idx - c*N384;
        int n1 = n0 + 2*c;
        float re = s0[idx].x * sc;
        float im = s0[idx].y * sc;
        float v1 = ((n1 + m) & 1) ? -re : re;
        float v2 = ((n1 + 1 + m) & 1) ? -im : im;
        float o1 = fmaf(mix, v1, om * cv[(2*c)*N384 + m]);
        float o2 = fmaf(mix, v2, om * cv[(2*c+1)*N384 + m]);
        int i1 = (2*c)*N384 + m, i2 = (2*c+1)*N384 + m;
        ob[i1]            = o1;  ob[i2]            = o2;
        ob[36*NPIX + i1]  = o1;  ob[36*NPIX + i2]  = o2;
        ob[72*NPIX + i1]  = o1;  ob[72*NPIX + i2]  = o2;
        ob[108*NPIX + i1] = o1;  ob[108*NPIX + i2] = o2;
    }
}

// ---------------- spatial 3x3 conv: 3 outputs per thread ---------------------
__global__ void __launch_bounds__(256)
k_conv(const float* __restrict__ x, const float* __restrict__ cw)
{
    __shared__ float scw[81];
    if (threadIdx.x < 81) scw[threadIdx.x] = cw[threadIdx.x];
    __syncthreads();

    int t = blockIdx.x*256 + threadIdx.x;
    int b = t / NPIX;
    int p = t - b*NPIX;
    int h = p / N384, w = p - h*N384;

    float acc0 = 0.f, acc1 = 0.f, acc2 = 0.f;
    bool hlo = (h > 0), hhi = (h < 383);
    bool wlo = (w > 0), whi = (w < 383);

    #pragma unroll
    for (int i = 0; i < 3; i++) {
        const float* xp = x + (size_t)(b*3+i)*NPIX + p;
        float v[9];
        v[0] = (hlo && wlo) ? xp[-N384-1] : 0.f;
        v[1] = (hlo       ) ? xp[-N384  ] : 0.f;
        v[2] = (hlo && whi) ? xp[-N384+1] : 0.f;
        v[3] = (       wlo) ? xp[-1]      : 0.f;
        v[4] =                xp[0];
        v[5] = (       whi) ? xp[1]       : 0.f;
        v[6] = (hhi && wlo) ? xp[N384-1]  : 0.f;
        v[7] = (hhi       ) ? xp[N384]    : 0.f;
        v[8] = (hhi && whi) ? xp[N384+1]  : 0.f;
        const float* w0 = scw + (0*3+i)*9;
        const float* w1 = scw + (1*3+i)*9;
        const float* w2 = scw + (2*3+i)*9;
        #pragma unroll
        for (int k = 0; k < 9; k++) {
            acc0 = fmaf(v[k], w0[k], acc0);
            acc1 = fmaf(v[k], w1[k], acc1);
            acc2 = fmaf(v[k], w2[k], acc2);
        }
    }
    g_Cv[(size_t)(b*3+0)*NPIX + p] = acc0;
    g_Cv[(size_t)(b*3+1)*NPIX + p] = acc1;
    g_Cv[(size_t)(b*3+2)*NPIX + p] = acc2;
}

// ------------------------------------------------------------------
extern "C" void kernel_launch(void* const* d_in, const int* in_sizes, int n_in,
                              void* d_out, int out_size)
{
    const float* x      = (const float*)d_in[0];
    const float* theta  = (const float*)d_in[1];
    const float* sigma  = (const float*)d_in[2];
    const float* f0     = (const float*)d_in[3];
    const float* theta0 = (const float*)d_in[4];
    const float* aw1    = (const float*)d_in[5];
    const float* ab1    = (const float*)d_in[6];
    const float* aw2    = (const float*)d_in[7];
    const float* ab2    = (const float*)d_in[8];
    const float* convw  = (const float*)d_in[9];
    const float* mixing = (const float*)d_in[10];
    const float* band   = (const float*)d_in[11];
    float* out = (float*)d_out;

    k_fwd_row<<<12*48, 256>>>(x);
    k_fwd_col<<<12*49, 256>>>();
    k_attn<<<NPIX/256, 256>>>(theta, sigma, f0, theta0, aw1, ab1, aw2, ab2);
    k_conv<<<4*NPIX/256, 256>>>(x, convw);
    k_inv_col<<<36*96, 256>>>(band);
    k_inv_rowout<<<36*48, 256>>>(band, mixing, out);
}

// round 6
// speedup vs baseline: 2.8262x; 1.2096x over previous
#include <cuda_runtime.h>
#include <cuda_bf16.h>
#include <math.h>

#define N384 384
#define NPIX (384*384)
#define PI_F 3.14159265358979323846f

// -------- scratch (static __device__ arrays; allocation is forbidden) --------
__device__ float2 g_A  [12*NPIX];   // forward row-pass result
__device__ float2 g_Xs [12*NPIX];   // shifted spectrum  [b*3+d][h][w]
__device__ float2 g_Att[ 4*NPIX];   // attended (shifted coords)
__device__ float2 g_Tmp[36*NPIX];   // inverse column-pass result (band cols only valid)
__device__ float  g_Cv [12*NPIX];   // spatial conv  [b][o][h][w]

__device__ __forceinline__ float2 cmul(float2 a, float2 b) {
    return make_float2(a.x*b.x - a.y*b.y, a.x*b.y + a.y*b.x);
}

// ------- 384-pt Stockham FFT: radix-3, 3x radix-4, radix-2 (5 stages) --------
// NC transforms in smem, layout s[c*384+e]. INPUT in s0, RESULT in s1.
// dir = -1 forward, +1 inverse. No normalization.
template<int NC>
__device__ void fft384_multi(float2* s0, float2* s1, int tid, int nt, float dir)
{
    __syncthreads();
    // ---- radix-3 (n=384, s=1): s0 -> s1 ----
    {
        const float th0 = dir * (2.0f * PI_F / 384.0f);
        const float s3  = dir * 0.8660254037844386f;
        const int total = NC * 128;
        for (int idx = tid; idx < total; idx += nt) {
            int c = idx >> 7;
            int p = idx & 127;
            const float2* x = s0 + c*N384;
            float2*       y = s1 + c*N384;
            float2 a = x[p], b = x[p+128], cc = x[p+256];
            float t1x = b.x+cc.x, t1y = b.y+cc.y;
            float t2x = b.x-cc.x, t2y = b.y-cc.y;
            float2 x0 = make_float2(a.x+t1x, a.y+t1y);
            float ux = a.x - 0.5f*t1x, uy = a.y - 0.5f*t1y;
            float vx = -s3*t2y,        vy =  s3*t2x;
            float2 x1 = make_float2(ux+vx, uy+vy);
            float2 x2 = make_float2(ux-vx, uy-vy);
            float cw, sw; __sincosf(th0 * (float)p, &sw, &cw);
            float2 w1 = make_float2(cw, sw);
            float2 w2 = cmul(w1, w1);
            y[3*p  ] = x0;
            y[3*p+1] = cmul(x1, w1);
            y[3*p+2] = cmul(x2, w2);
        }
        __syncthreads();
    }
    // ---- 3 radix-4 stages: (128,3) s1->s0, (32,12) s0->s1, (8,48) s1->s0 ----
    #pragma unroll
    for (int stage = 0; stage < 3; stage++) {
        const int nn = (stage==0) ? 128 : (stage==1) ? 32 : 8;
        const int ss = (stage==0) ?   3 : (stage==1) ? 12 : 48;
        const int n4 = nn >> 2;
        float2* src = (stage==1) ? s0 : s1;
        float2* dst = (stage==1) ? s1 : s0;
        const float th0 = dir * (2.0f * PI_F / (float)nn);
        const int total = NC * 96;
        for (int idx = tid; idx < total; idx += nt) {
            int c = idx / 96;
            int r = idx - c*96;
            int p = r / ss;           // ss is a compile-time literal after unroll
            int q = r - p*ss;
            const float2* x = src + c*N384;
            float2*       y = dst + c*N384;
            float2 x0 = x[q + ss*p];
            float2 x1 = x[q + ss*(p +   n4)];
            float2 x2 = x[q + ss*(p + 2*n4)];
            float2 x3 = x[q + ss*(p + 3*n4)];
            float2 e0 = make_float2(x0.x+x2.x, x0.y+x2.y);
            float2 e1 = make_float2(x1.x+x3.x, x1.y+x3.y);
            float2 d0 = make_float2(x0.x-x2.x, x0.y-x2.y);
            float2 d1 = make_float2(x1.x-x3.x, x1.y-x3.y);
            float2 id1 = make_float2(-dir*d1.y, dir*d1.x);   // dir*i * d1
            float2 u0 = make_float2(e0.x+e1.x,  e0.y+e1.y);
            float2 u1 = make_float2(d0.x+id1.x, d0.y+id1.y);
            float2 u2 = make_float2(e0.x-e1.x,  e0.y-e1.y);
            float2 u3 = make_float2(d0.x-id1.x, d0.y-id1.y);
            float cw, sw; __sincosf(th0 * (float)p, &sw, &cw);
            float2 w1 = make_float2(cw, sw);
            float2 w2 = cmul(w1, w1);
            float2 w3 = cmul(w2, w1);
            y[q + ss*(4*p)  ] = u0;
            y[q + ss*(4*p+1)] = cmul(u1, w1);
            y[q + ss*(4*p+2)] = cmul(u2, w2);
            y[q + ss*(4*p+3)] = cmul(u3, w3);
        }
        __syncthreads();
    }
    // ---- final radix-2 (n=2, s=192, twiddle = 1): s0 -> s1 ----
    {
        const int total = NC * 192;
        for (int idx = tid; idx < total; idx += nt) {
            int c = idx / 192;
            int q = idx - c*192;
            const float2* x = s0 + c*N384;
            float2*       y = s1 + c*N384;
            float2 a = x[q], b = x[q+192];
            y[q]     = make_float2(a.x+b.x, a.y+b.y);
            y[q+192] = make_float2(a.x-b.x, a.y-b.y);
        }
        __syncthreads();
    }
}

// -------- forward row pass: real-input packing, 8 rows (4 packed FFTs)/block --
__global__ void k_fwd_row(const float* __restrict__ x)
{
    __shared__ float2 s0[4*N384], s1[4*N384];
    int img  = blockIdx.x / 48;
    int tile = blockIdx.x - img*48;
    int r0 = tile * 8;
    int b = img / 3, d = img - b*3;
    int bs = (b + 2) & 3;
    int ds = (d + 2) % 3;
    const float* xr = x + ((size_t)(bs*3 + ds)*NPIX) + (size_t)r0*N384;
    for (int idx = threadIdx.x; idx < 4*N384; idx += blockDim.x) {
        int c = idx / N384, w = idx - c*N384;
        s0[idx] = make_float2(xr[(2*c)*N384 + w], xr[(2*c+1)*N384 + w]);
    }
    fft384_multi<4>(s0, s1, threadIdx.x, blockDim.x, -1.f);
    float2* out = g_A + (size_t)img*NPIX + (size_t)r0*N384;
    for (int idx = threadIdx.x; idx < 4*N384; idx += blockDim.x) {
        int c = idx / N384, w = idx - c*N384;
        int mw = (w == 0) ? 0 : (N384 - w);
        float2 F1 = s1[c*N384 + w];
        float2 F2 = s1[c*N384 + mw];          // conj taken below
        float2 ev = make_float2(0.5f*(F1.x + F2.x), 0.5f*(F1.y - F2.y));
        float dx = F1.x - F2.x, dy = F1.y + F2.y;
        float2 od = make_float2(0.5f*dy, -0.5f*dx);
        out[(2*c)*N384 + w]   = ev;
        out[(2*c+1)*N384 + w] = od;
    }
}

// -------- forward column pass: Hermitian halving (+h,w shift) ----------------
__global__ void k_fwd_col()
{
    __shared__ float2 s0[4*N384], s1[4*N384];
    int img  = blockIdx.x / 49;
    int tile = blockIdx.x - img*49;
    int c0 = tile * 4;                      // columns 0..195 computed
    const float2* A = g_A + (size_t)img*NPIX;
    for (int idx = threadIdx.x; idx < 4*N384; idx += blockDim.x) {
        int h = idx >> 2, c = idx & 3;
        s0[c*N384 + h] = A[h*N384 + c0 + c];
    }
    fft384_multi<4>(s0, s1, threadIdx.x, blockDim.x, -1.f);
    float2* Xs = g_Xs + (size_t)img*NPIX;
    for (int idx = threadIdx.x; idx < 4*N384; idx += blockDim.x) {
        int hh = idx >> 2, c = idx & 3;
        int l = c0 + c;
        float2 v = s1[c*N384 + hh];
        if (l <= 192) {
            int h2 = hh + 192; if (h2 >= N384) h2 -= N384;
            int w2 = l + 192;  if (w2 >= N384) w2 -= N384;
            Xs[h2*N384 + w2] = v;
        }
        if (l >= 1 && l <= 191) {
            int hm = ((N384 - hh) % N384) + 192; if (hm >= N384) hm -= N384;
            int wm = 192 - l;
            Xs[hm*N384 + wm] = make_float2(v.x, -v.y);
        }
    }
}

// ---------------- attention MLP + log-Gabor bank + attended ------------------
__global__ void __launch_bounds__(256)
k_attn(const float* __restrict__ theta, const float* __restrict__ sigma,
       const float* __restrict__ f0,    const float* __restrict__ theta0,
       const float* __restrict__ w1,    const float* __restrict__ b1,
       const float* __restrict__ w2,    const float* __restrict__ b2)
{
    __shared__ float sw1[192], sb1[64], sw2[576], sb2[9];
    __shared__ float sth[27], slf0[27], sc1[27], sc2[27];
    __shared__ int s_uni;
    int tid = threadIdx.x;
    for (int i = tid; i < 192; i += 256) sw1[i] = w1[i];
    for (int i = tid; i < 576; i += 256) sw2[i] = w2[i];
    if (tid < 64) sb1[tid] = b1[tid];
    if (tid < 9)  sb2[tid] = b2[tid];
    if (tid < 27) {
        sth[tid]  = theta[tid];
        float ls  = __logf(sigma[tid]);
        sc1[tid]  = -0.5f / (ls*ls);
        float t0  = theta0[tid];
        sc2[tid]  = -0.5f / (t0*t0);
        slf0[tid] = __logf(f0[tid]);
    }
    __syncthreads();
    if (tid == 0) {
        int u = 1;
        #pragma unroll
        for (int i = 1; i < 27; i++) if (slf0[i] != slf0[0]) u = 0;
        s_uni = u;
    }
    __syncthreads();
    const int uni = s_uni;

    int p = blockIdx.x*256 + tid;

    float mag[12];
    #pragma unroll
    for (int i = 0; i < 12; i++) {
        float2 X = g_Xs[(size_t)i*NPIX + p];
        mag[i] = sqrtf(X.x*X.x + X.y*X.y);
    }

    float logit[36];
    #pragma unroll
    for (int b = 0; b < 4; b++)
        #pragma unroll
        for (int o = 0; o < 9; o++) logit[b*9+o] = sb2[o];
    for (int j = 0; j < 64; j++) {
        float a0 = sw1[j*3], a1 = sw1[j*3+1], a2 = sw1[j*3+2], bb = sb1[j];
        float t0 = fmaxf(fmaf(a2, mag[2],  fmaf(a1, mag[1],  fmaf(a0, mag[0],  bb))), 0.f);
        float t1 = fmaxf(fmaf(a2, mag[5],  fmaf(a1, mag[4],  fmaf(a0, mag[3],  bb))), 0.f);
        float t2 = fmaxf(fmaf(a2, mag[8],  fmaf(a1, mag[7],  fmaf(a0, mag[6],  bb))), 0.f);
        float t3 = fmaxf(fmaf(a2, mag[11], fmaf(a1, mag[10], fmaf(a0, mag[9],  bb))), 0.f);
        #pragma unroll
        for (int o = 0; o < 9; o++) {
            float wv = sw2[o*64+j];
            logit[o]    = fmaf(wv, t0, logit[o]);
            logit[9+o]  = fmaf(wv, t1, logit[9+o]);
            logit[18+o] = fmaf(wv, t2, logit[18+o]);
            logit[27+o] = fmaf(wv, t3, logit[27+o]);
        }
    }

    int h = p / N384, w = p - h*N384;
    float yy = -1.f + (2.f/383.f) * (float)h;
    float xx = -1.f + (2.f/383.f) * (float)w;
    float r   = sqrtf(xx*xx + yy*yy + 1e-6f);
    float phi = atan2f(yy, xx);
    float filt[27];
    if (uni) {
        float lr = __logf(r - slf0[0]);
        float lr2 = lr*lr;
        #pragma unroll
        for (int i = 0; i < 27; i++) {
            float dph = phi - sth[i];
            filt[i] = __expf(fmaf(lr2, sc1[i], dph*dph*sc2[i]));
        }
    } else {
        #pragma unroll
        for (int i = 0; i < 27; i++) {
            float lr = __logf(r - slf0[i]);
            float dph = phi - sth[i];
            filt[i] = __expf(fmaf(lr*lr, sc1[i], dph*dph*sc2[i]));
        }
    }

    #pragma unroll
    for (int b = 0; b < 4; b++) {
        float* lg = logit + b*9;
        float mx = lg[0];
        #pragma unroll
        for (int o = 1; o < 9; o++) mx = fmaxf(mx, lg[o]);
        float att[9], ssum = 0.f;
        #pragma unroll
        for (int o = 0; o < 9; o++) { att[o] = __expf(lg[o]-mx); ssum += att[o]; }
        float inv = __fdividef(1.f, ssum);
        float wg0=0.f, wg1=0.f, wg2=0.f;
        #pragma unroll
        for (int sc = 0; sc < 9; sc++) {
            float a = att[sc] * inv;
            wg0 = fmaf(a, filt[sc*3+0], wg0);
            wg1 = fmaf(a, filt[sc*3+1], wg1);
            wg2 = fmaf(a, filt[sc*3+2], wg2);
        }
        float2 X0 = g_Xs[(size_t)(b*3+0)*NPIX + p];
        float2 X1 = g_Xs[(size_t)(b*3+1)*NPIX + p];
        float2 X2 = g_Xs[(size_t)(b*3+2)*NPIX + p];
        float2 acc;
        acc.x = X0.x*wg0 + X1.x*wg1 + X2.x*wg2;
        acc.y = X0.y*wg0 + X1.y*wg1 + X2.y*wg2;
        g_Att[(size_t)b*NPIX + p] = acc;
    }
}

// ---------------- inverse: column pass with band mask (pruned) ---------------
__global__ void k_inv_col(const float* __restrict__ band)
{
    __shared__ float2 s0[4*N384], s1[4*N384];
    int plane = blockIdx.x / 96;
    int tile  = blockIdx.x - plane*96;
    int kap  = plane / 12;
    int rest = plane - kap*12;
    int del  = rest / 4;
    int beta = rest - del*4;
    float b0 = band[(kap*3+del)*2+0], b1 = band[(kap*3+del)*2+1];
    int si = (int)floorf((b0+1.f)*0.5f*384.f);
    int ei = (int)floorf((b1+1.f)*0.5f*384.f);
    int c0 = tile * 4;
    if (si >= ei || c0 >= ei || c0+4 <= si) return;

    const float2* At = g_Att + (size_t)beta*NPIX;
    for (int idx = threadIdx.x; idx < 4*N384; idx += blockDim.x) {
        int h = idx >> 2, c = idx & 3;
        int wc = c0 + c;
        float2 v = make_float2(0.f, 0.f);
        if (wc >= si && wc < ei && h >= si && h < ei)
            v = At[h*N384 + wc];
        s0[c*N384 + h] = v;
    }
    fft384_multi<4>(s0, s1, threadIdx.x, blockDim.x, +1.f);
    float2* T = g_Tmp + (size_t)plane*NPIX;
    const float sc = 1.f/384.f;
    for (int idx = threadIdx.x; idx < 4*N384; idx += blockDim.x) {
        int n = idx >> 2, c = idx & 3;
        int wc = c0 + c;
        if (wc >= si && wc < ei) {
            float2 v = s1[c*N384 + n];
            T[n*N384 + wc] = make_float2(v.x*sc, v.y*sc);
        }
    }
}

// -- inverse row pass: Hermitian-packed (2 real rows per FFT) + mix/assembly --
__global__ void k_inv_rowout(const float* __restrict__ band,
                             const float* __restrict__ mixing,
                             float* __restrict__ out)
{
    __shared__ float2 s0[4*N384], s1[4*N384];
    int plane = blockIdx.x / 48;
    int tile  = blockIdx.x - plane*48;
    int n0 = tile * 8;                       // 8 output rows, 4 packed FFTs
    int kap  = plane / 12;
    int rest = plane - kap*12;
    int del  = rest / 4;
    int beta = rest - del*4;
    int co = (kap + 2) % 3;
    int ci = (del + 2) % 3;
    int b  = (beta + 2) & 3;
    float b0 = band[(kap*3+del)*2+0], b1 = band[(kap*3+del)*2+1];
    int si = (int)floorf((b0+1.f)*0.5f*384.f);
    int ei = (int)floorf((b1+1.f)*0.5f*384.f);
    float mix = mixing[0];
    float om  = 1.f - mix;
    const float* cv = g_Cv + (size_t)(b*3+ci)*NPIX + (size_t)n0*N384;
    float* ob = out + (size_t)(co*12 + b*3 + ci)*NPIX + (size_t)n0*N384;

    if (si >= ei) {                           // plane contributes zero
        for (int idx = threadIdx.x; idx < 8*N384; idx += blockDim.x) {
            float v = om * cv[idx];
            ob[idx]            = v;
            ob[36*NPIX + idx]  = v;
            ob[72*NPIX + idx]  = v;
            ob[108*NPIX + idx] = v;
        }
        return;
    }

    // zero, then scatter Hermitian-symmetrized packed rows
    for (int idx = threadIdx.x; idx < 4*N384; idx += blockDim.x)
        s0[idx] = make_float2(0.f, 0.f);
    __syncthreads();
    const float2* Tm = g_Tmp + (size_t)plane*NPIX;
    int K = ei - si;
    for (int j = threadIdx.x; j < 4*K; j += blockDim.x) {
        int c = j & 3;
        int l = si + (j >> 2);
        float2 T1 = Tm[(size_t)(n0 + 2*c)*N384 + l];
        float2 T2 = Tm[(size_t)(n0 + 2*c + 1)*N384 + l];
        float2 zl = make_float2(T1.x - T2.y, T1.y + T2.x);   // T1 + i*T2
        float2 zm = make_float2(T1.x + T2.y, T2.x - T1.y);   // conj(T1) + i*conj(T2)
        int lm = N384 - l;
        if (lm == l) {
            s0[c*N384 + l] = make_float2(zl.x + zm.x, zl.y + zm.y);
        } else {
            s0[c*N384 + l]  = zl;
            s0[c*N384 + lm] = zm;
        }
    }
    fft384_multi<4>(s0, s1, threadIdx.x, blockDim.x, +1.f);
    const float sc = 1.f/768.f;               // 1/(2*384)
    for (int idx = threadIdx.x; idx < 4*N384; idx += blockDim.x) {
        int c = idx / N384, m = idx - c*N384;
        int n1 = n0 + 2*c;
        float re = s1[idx].x * sc;
        float im = s1[idx].y * sc;
        float v1 = ((n1 + m) & 1) ? -re : re;
        float v2 = ((n1 + 1 + m) & 1) ? -im : im;
        float o1 = fmaf(mix, v1, om * cv[(2*c)*N384 + m]);
        float o2 = fmaf(mix, v2, om * cv[(2*c+1)*N384 + m]);
        int i1 = (2*c)*N384 + m, i2 = (2*c+1)*N384 + m;
        ob[i1]            = o1;  ob[i2]            = o2;
        ob[36*NPIX + i1]  = o1;  ob[36*NPIX + i2]  = o2;
        ob[72*NPIX + i1]  = o1;  ob[72*NPIX + i2]  = o2;
        ob[108*NPIX + i1] = o1;  ob[108*NPIX + i2] = o2;
    }
}

// ---------------- spatial 3x3 conv: 3 outputs per thread ---------------------
__global__ void __launch_bounds__(256)
k_conv(const float* __restrict__ x, const float* __restrict__ cw)
{
    __shared__ float scw[81];
    if (threadIdx.x < 81) scw[threadIdx.x] = cw[threadIdx.x];
    __syncthreads();

    int t = blockIdx.x*256 + threadIdx.x;
    int b = t / NPIX;
    int p = t - b*NPIX;
    int h = p / N384, w = p - h*N384;

    float acc0 = 0.f, acc1 = 0.f, acc2 = 0.f;
    bool hlo = (h > 0), hhi = (h < 383);
    bool wlo = (w > 0), whi = (w < 383);

    #pragma unroll
    for (int i = 0; i < 3; i++) {
        const float* xp = x + (size_t)(b*3+i)*NPIX + p;
        float v[9];
        v[0] = (hlo && wlo) ? xp[-N384-1] : 0.f;
        v[1] = (hlo       ) ? xp[-N384  ] : 0.f;
        v[2] = (hlo && whi) ? xp[-N384+1] : 0.f;
        v[3] = (       wlo) ? xp[-1]      : 0.f;
        v[4] =                xp[0];
        v[5] = (       whi) ? xp[1]       : 0.f;
        v[6] = (hhi && wlo) ? xp[N384-1]  : 0.f;
        v[7] = (hhi       ) ? xp[N384]    : 0.f;
        v[8] = (hhi && whi) ? xp[N384+1]  : 0.f;
        const float* w0 = scw + (0*3+i)*9;
        const float* w1 = scw + (1*3+i)*9;
        const float* w2 = scw + (2*3+i)*9;
        #pragma unroll
        for (int k = 0; k < 9; k++) {
            acc0 = fmaf(v[k], w0[k], acc0);
            acc1 = fmaf(v[k], w1[k], acc1);
            acc2 = fmaf(v[k], w2[k], acc2);
        }
    }
    g_Cv[(size_t)(b*3+0)*NPIX + p] = acc0;
    g_Cv[(size_t)(b*3+1)*NPIX + p] = acc1;
    g_Cv[(size_t)(b*3+2)*NPIX + p] = acc2;
}

// ------------------------------------------------------------------
extern "C" void kernel_launch(void* const* d_in, const int* in_sizes, int n_in,
                              void* d_out, int out_size)
{
    const float* x      = (const float*)d_in[0];
    const float* theta  = (const float*)d_in[1];
    const float* sigma  = (const float*)d_in[2];
    const float* f0     = (const float*)d_in[3];
    const float* theta0 = (const float*)d_in[4];
    const float* aw1    = (const float*)d_in[5];
    const float* ab1    = (const float*)d_in[6];
    const float* aw2    = (const float*)d_in[7];
    const float* ab2    = (const float*)d_in[8];
    const float* convw  = (const float*)d_in[9];
    const float* mixing = (const float*)d_in[10];
    const float* band   = (const float*)d_in[11];
    float* out = (float*)d_out;

    k_fwd_row<<<12*48, 256>>>(x);
    k_fwd_col<<<12*49, 256>>>();
    k_attn<<<NPIX/256, 256>>>(theta, sigma, f0, theta0, aw1, ab1, aw2, ab2);
    k_conv<<<4*NPIX/256, 256>>>(x, convw);
    k_inv_col<<<36*96, 256>>>(band);
    k_inv_rowout<<<36*48, 256>>>(band, mixing, out);
}